// round 11
// baseline (speedup 1.0000x reference)
#include <cuda_runtime.h>
#include <cuda_bf16.h>
#include <math.h>

#define B 32
#define T 128
#define BT 4096
#define E 1024
#define H 1024
#define G 4096
#define V 32000

typedef unsigned long long ull;

// ---------------- cp.async helpers ----------------
__device__ __forceinline__ void cp_async16_s(unsigned dst, const void* gptr) {
    asm volatile("cp.async.cg.shared.global [%0], [%1], 16;\n" :: "r"(dst), "l"(gptr));
}
__device__ __forceinline__ void cp_async_commit() {
    asm volatile("cp.async.commit_group;\n");
}
__device__ __forceinline__ void cp_async_wait_all() {
    asm volatile("cp.async.wait_group 0;\n" ::: "memory");
}

// ---------------- mma.sync / ldmatrix helpers ----------------
__device__ __forceinline__ void ldm4(unsigned* r, unsigned addr) {
    asm volatile("ldmatrix.sync.aligned.m8n8.x4.shared.b16 {%0,%1,%2,%3}, [%4];"
                 : "=r"(r[0]), "=r"(r[1]), "=r"(r[2]), "=r"(r[3]) : "r"(addr));
}
__device__ __forceinline__ void mma_bf16(float* c, const unsigned* a, unsigned b0, unsigned b1) {
    asm volatile(
        "mma.sync.aligned.m16n8k16.row.col.f32.bf16.bf16.f32 "
        "{%0,%1,%2,%3}, {%4,%5,%6,%7}, {%8,%9}, {%0,%1,%2,%3};"
        : "+f"(c[0]), "+f"(c[1]), "+f"(c[2]), "+f"(c[3])
        : "r"(a[0]), "r"(a[1]), "r"(a[2]), "r"(a[3]), "r"(b0), "r"(b1));
}
__device__ __forceinline__ unsigned swz(unsigned off) {
    return off ^ ((off >> 3) & 0x70);
}

// ---------------- device scratch ----------------
__device__ __align__(16) float g_gxA[BT * G];          // layer-0 input gates (t-major rows)
__device__ __align__(16) float g_gxB[BT * G];          // layer-1 input gates (t-major rows)
__device__ __align__(16) float g_c[B * H];
// t-major bf16 hi/lo activations
__device__ __align__(16) __nv_bfloat16 g_xahi[BT * H];
__device__ __align__(16) __nv_bfloat16 g_xalo[BT * H];
__device__ __align__(16) __nv_bfloat16 g_s0hi[BT * H];
__device__ __align__(16) __nv_bfloat16 g_s0lo[BT * H];
__device__ __align__(16) __nv_bfloat16 g_s1hi[BT * H];
__device__ __align__(16) __nv_bfloat16 g_s1lo[BT * H];
// zero h for t=0
__device__ __align__(16) __nv_bfloat16 g_hzh[B * H];
__device__ __align__(16) __nv_bfloat16 g_hzl[B * H];
// dense weights (transposed [n][k], hi/lo)
__device__ __align__(16) __nv_bfloat16 g_bhi[(size_t)V * H];
__device__ __align__(16) __nv_bfloat16 g_blo[(size_t)V * H];
// x-path weights, transposed [n][k]
__device__ __align__(16) __nv_bfloat16 g_w0xhi[G * H];
__device__ __align__(16) __nv_bfloat16 g_w0xlo[G * H];
__device__ __align__(16) __nv_bfloat16 g_w1xhi[G * H];
__device__ __align__(16) __nv_bfloat16 g_w1xlo[G * H];
// recurrent weights, transposed + gate-block permuted [prow][k]
__device__ __align__(16) __nv_bfloat16 g_wh0hi[G * H];
__device__ __align__(16) __nv_bfloat16 g_wh0lo[G * H];
__device__ __align__(16) __nv_bfloat16 g_wh1hi[G * H];
__device__ __align__(16) __nv_bfloat16 g_wh1lo[G * H];

// ---------------- embedding gather + bf16 hi/lo split (t-major) ----------------
__global__ void embed_split_kernel(const int* __restrict__ idx, const float* __restrict__ emb) {
    int r = blockIdx.x;                 // r = b*T + t
    int b = r >> 7, t = r & 127;
    int drow = t * B + b;
    int tok = idx[r];
    float4 v = ((const float4*)(emb + (size_t)tok * E))[threadIdx.x];
    int o = drow * H + threadIdx.x * 4;
    float f[4] = {v.x, v.y, v.z, v.w};
#pragma unroll
    for (int i = 0; i < 4; i++) {
        __nv_bfloat16 hi = __float2bfloat16(f[i]);
        __nv_bfloat16 lo = __float2bfloat16(f[i] - __bfloat162float(hi));
        g_xahi[o + i] = hi;
        g_xalo[o + i] = lo;
    }
}

// zero c and the t=0 h buffers
__global__ void zero_state_kernel() {
    int i = blockIdx.x * blockDim.x + threadIdx.x;
    if (i < B * H) {
        g_c[i] = 0.f;
        g_hzh[i] = __float2bfloat16(0.f);
        g_hzl[i] = __float2bfloat16(0.f);
    }
}

// ---------------- weight converts ----------------
// transpose-convert src[k][N] fp32 -> dhi/dlo[n][1024] bf16 (K = 1024)
__global__ __launch_bounds__(256) void convert_wt(
    const float* __restrict__ src, __nv_bfloat16* __restrict__ dhi,
    __nv_bfloat16* __restrict__ dlo, int N)
{
    __shared__ float tile[32][33];
    int tx = threadIdx.x & 31, ty = threadIdx.x >> 5;
    int n0 = blockIdx.x * 32, k0 = blockIdx.y * 32;
#pragma unroll
    for (int i = 0; i < 4; i++)
        tile[ty + 8 * i][tx] = src[(size_t)(k0 + ty + 8 * i) * N + n0 + tx];
    __syncthreads();
#pragma unroll
    for (int i = 0; i < 4; i++) {
        float v = tile[tx][ty + 8 * i];
        __nv_bfloat16 hi = __float2bfloat16(v);
        __nv_bfloat16 lo = __float2bfloat16(v - __bfloat162float(hi));
        size_t o = (size_t)(n0 + ty + 8 * i) * H + k0 + tx;
        dhi[o] = hi;
        dlo[o] = lo;
    }
}

// gate-block permuted: n = g*1024 + j -> prow = (j/8)*32 + g*8 + (j%8)
__global__ __launch_bounds__(256) void convert_wt_perm(
    const float* __restrict__ src, __nv_bfloat16* __restrict__ dhi,
    __nv_bfloat16* __restrict__ dlo)
{
    __shared__ float tile[32][33];
    int tx = threadIdx.x & 31, ty = threadIdx.x >> 5;
    int n0 = blockIdx.x * 32, k0 = blockIdx.y * 32;
#pragma unroll
    for (int i = 0; i < 4; i++)
        tile[ty + 8 * i][tx] = src[(size_t)(k0 + ty + 8 * i) * G + n0 + tx];
    __syncthreads();
#pragma unroll
    for (int i = 0; i < 4; i++) {
        float v = tile[tx][ty + 8 * i];
        __nv_bfloat16 hi = __float2bfloat16(v);
        __nv_bfloat16 lo = __float2bfloat16(v - __bfloat162float(hi));
        int n = n0 + ty + 8 * i;
        int g = n >> 10, j = n & 1023;
        int prow = (j >> 3) * 32 + g * 8 + (j & 7);
        size_t o = (size_t)prow * H + k0 + tx;
        dhi[o] = hi;
        dlo[o] = lo;
    }
}

// ---------------- generic HMMA GEMM: C = A @ B^T + bias (3-pass hi/lo) ----------------
// Block tile 128x128, 8 warps (2m x 4n), K chunks of 64.
// remap=1: A rows are t-major (row = t*32+b), C rows are b*T+t (dense out).
#define DTILE 16384
#define DSTAGE (4 * DTILE)
#define DENSE_SMEM (2 * DSTAGE)

__device__ __forceinline__ void hmma_load(
    unsigned sbase, int m0, int n0, int kc,
    const __nv_bfloat16* Ahi, const __nv_bfloat16* Alo,
    const __nv_bfloat16* Bhi, const __nv_bfloat16* Blo)
{
    int tid = threadIdx.x;
#pragma unroll
    for (int i = 0; i < 16; i++) {
        int idx = tid + i * 256;
        int tl = idx >> 10;           // 0=Ahi 1=Alo 2=Bhi 3=Blo
        int j = idx & 1023;
        int r = j >> 3, c = j & 7;
        const __nv_bfloat16* gb = (tl == 0) ? Ahi : (tl == 1) ? Alo
                                 : (tl == 2) ? Bhi : Blo;
        int grow = ((tl < 2) ? m0 : n0) + r;
        const __nv_bfloat16* src = gb + (size_t)grow * H + kc * 64 + c * 8;
        unsigned dst = sbase + tl * DTILE + swz((unsigned)(r * 128 + c * 16));
        cp_async16_s(dst, src);
    }
}

__global__ __launch_bounds__(256, 1) void hmma_gemm(
    const __nv_bfloat16* __restrict__ Ahi, const __nv_bfloat16* __restrict__ Alo,
    const __nv_bfloat16* __restrict__ Bhi, const __nv_bfloat16* __restrict__ Blo,
    const float* __restrict__ bias, float* __restrict__ C, int N,
    int m_base, int remap)
{
    extern __shared__ __align__(128) char dsm[];
    unsigned sb = (unsigned)__cvta_generic_to_shared(dsm);
    int tid = threadIdx.x;
    int wid = tid >> 5, lane = tid & 31;
    int m0 = (m_base + blockIdx.x) * 128, n0 = blockIdx.y * 128;
    int wm = (wid & 1) * 64;
    int wn = (wid >> 1) * 32;
    int lrow = lane & 15, lch = lane >> 4;

    float acc[4][4][4];
#pragma unroll
    for (int mi = 0; mi < 4; mi++)
#pragma unroll
        for (int nj = 0; nj < 4; nj++)
#pragma unroll
            for (int q = 0; q < 4; q++) acc[mi][nj][q] = 0.f;

    hmma_load(sb, m0, n0, 0, Ahi, Alo, Bhi, Blo);
    cp_async_commit();

    for (int kc = 0; kc < 16; kc++) {
        int d = kc & 1;
        unsigned stage = sb + d * DSTAGE;
        cp_async_wait_all();
        __syncthreads();
        if (kc + 1 < 16) {
            hmma_load(sb + (d ^ 1) * DSTAGE, m0, n0, kc + 1, Ahi, Alo, Bhi, Blo);
            cp_async_commit();
        }

#pragma unroll
        for (int p = 0; p < 3; p++) {
            unsigned Ab = stage + ((p == 2) ? DTILE : 0);
            unsigned Bb = stage + 2 * DTILE + ((p == 1) ? DTILE : 0);
#pragma unroll
            for (int ks = 0; ks < 4; ks++) {
                unsigned a[4][4];
#pragma unroll
                for (int mi = 0; mi < 4; mi++) {
                    unsigned addr = Ab + swz((unsigned)((wm + mi * 16 + lrow) * 128
                                                        + ks * 32 + lch * 16));
                    ldm4(a[mi], addr);
                }
                unsigned bq[2][4];
#pragma unroll
                for (int bi = 0; bi < 2; bi++) {
                    unsigned addr = Bb + swz((unsigned)((wn + bi * 16 + lrow) * 128
                                                        + ks * 32 + lch * 16));
                    ldm4(bq[bi], addr);
                }
#pragma unroll
                for (int mi = 0; mi < 4; mi++)
#pragma unroll
                    for (int bi = 0; bi < 2; bi++) {
                        mma_bf16(acc[mi][bi * 2 + 0], a[mi], bq[bi][0], bq[bi][2]);
                        mma_bf16(acc[mi][bi * 2 + 1], a[mi], bq[bi][1], bq[bi][3]);
                    }
            }
        }
        __syncthreads();
    }

    int gid = lane >> 2, tig = lane & 3;
#pragma unroll
    for (int mi = 0; mi < 4; mi++) {
#pragma unroll
        for (int nj = 0; nj < 4; nj++) {
            int gr0 = m0 + wm + mi * 16 + gid;
            int gr1 = gr0 + 8;
            int or0 = remap ? ((gr0 & 31) * T + (gr0 >> 5)) : gr0;
            int or1 = remap ? ((gr1 & 31) * T + (gr1 >> 5)) : gr1;
            int col = n0 + wn + nj * 8 + tig * 2;
            float b0 = bias[col], b1 = bias[col + 1];
            float2 o0, o1;
            o0.x = acc[mi][nj][0] + b0; o0.y = acc[mi][nj][1] + b1;
            o1.x = acc[mi][nj][2] + b0; o1.y = acc[mi][nj][3] + b1;
            *(float2*)(C + (size_t)or0 * N + col) = o0;
            *(float2*)(C + (size_t)or1 * N + col) = o1;
        }
    }
}

// ---------------- HMMA LSTM timestep v2 ----------------
// 128 blocks; block bx owns hidden units j0 = bx*8..+7 (32 permuted weight rows).
// K = 1024 in 4 chunks of 256, double-buffered. gx slice + c prefetched to smem.
// smem: 2 stages x 64KB | red 32KB | gxs 4KB | cs 1KB
#define RSTG 65536
#define R_RED (2 * RSTG)
#define R_GX (R_RED + 32768)
#define R_CS (R_GX + 4096)
#define R_SMEM (R_CS + 1024)

__device__ __forceinline__ void lstm_stage_load(
    unsigned base, int kc,
    const __nv_bfloat16* hin_hi, const __nv_bfloat16* hin_lo,
    const __nv_bfloat16* whhi, const __nv_bfloat16* whlo, int n0)
{
    int tid = threadIdx.x;
#pragma unroll
    for (int i = 0; i < 16; i++) {
        int idx = tid + i * 256;
        int part = idx >> 10;         // 0=Ahi 1=Alo 2=Bhi 3=Blo
        int j = idx & 1023;
        int sub = j >> 8, jj = j & 255;
        int r = jj >> 3, c8 = jj & 7;
        int koff = kc * 256 + sub * 64 + c8 * 8;
        const __nv_bfloat16* src;
        if (part == 0)      src = hin_hi + r * H + koff;
        else if (part == 1) src = hin_lo + r * H + koff;
        else if (part == 2) src = whhi + (size_t)(n0 + r) * H + koff;
        else                src = whlo + (size_t)(n0 + r) * H + koff;
        unsigned dst = base + part * 16384 + sub * 4096 + swz((unsigned)(r * 128 + c8 * 16));
        cp_async16_s(dst, src);
    }
}

__global__ __launch_bounds__(256, 1) void lstm_hmma(
    const float* __restrict__ gx,
    const __nv_bfloat16* __restrict__ whhi, const __nv_bfloat16* __restrict__ whlo,
    const __nv_bfloat16* __restrict__ hin_hi, const __nv_bfloat16* __restrict__ hin_lo,
    __nv_bfloat16* __restrict__ hout_hi, __nv_bfloat16* __restrict__ hout_lo,
    float* __restrict__ c_st, int t)
{
    extern __shared__ __align__(128) char rsm[];
    unsigned sb = (unsigned)__cvta_generic_to_shared(rsm);
    float* red = (float*)(rsm + R_RED);
    float* gxs = (float*)(rsm + R_GX);
    float* cs  = (float*)(rsm + R_CS);
    int tid = threadIdx.x, wid = tid >> 5, lane = tid & 31;
    int n0 = blockIdx.x * 32;
    int j0 = blockIdx.x * 8;

    lstm_stage_load(sb, 0, hin_hi, hin_lo, whhi, whlo, n0);
    // prefetch gx slice and c state into smem
    {
        int b = tid >> 3, g = (tid >> 1) & 3, hf = tid & 1;
        cp_async16_s(sb + R_GX + (unsigned)(b * 32 + g * 8 + hf * 4) * 4,
                     gx + (size_t)(t * B + b) * G + g * H + j0 + hf * 4);
        if (tid < 64) {
            int b2 = tid >> 1, hf2 = tid & 1;
            cp_async16_s(sb + R_CS + (unsigned)(b2 * 8 + hf2 * 4) * 4,
                         c_st + b2 * H + j0 + hf2 * 4);
        }
    }
    cp_async_commit();

    float acc[2][4][4];
#pragma unroll
    for (int mi = 0; mi < 2; mi++)
#pragma unroll
        for (int nj = 0; nj < 4; nj++)
#pragma unroll
            for (int q = 0; q < 4; q++) acc[mi][nj][q] = 0.f;

    int sub = wid >> 1, half = wid & 1;
    int lrow = lane & 15, lch = lane >> 4;

    for (int c = 0; c < 4; c++) {
        int d = c & 1;
        unsigned stage = sb + d * RSTG;
        cp_async_wait_all();
        __syncthreads();
        if (c + 1 < 4) {
            lstm_stage_load(sb + (d ^ 1) * RSTG, c + 1, hin_hi, hin_lo, whhi, whlo, n0);
            cp_async_commit();
        }

        unsigned Ah = stage + sub * 4096;
        unsigned Al = stage + 16384 + sub * 4096;
        unsigned Bh = stage + 32768 + sub * 4096;
        unsigned Bl = stage + 49152 + sub * 4096;

#pragma unroll
        for (int ki = 0; ki < 2; ki++) {
            unsigned kb = (unsigned)((half * 2 + ki) * 32);
            unsigned ahi[2][4], alo[2][4], bhi[2][4], blo[2][4];
#pragma unroll
            for (int mi = 0; mi < 2; mi++) {
                unsigned off = swz((unsigned)((mi * 16 + lrow) * 128) + kb + (unsigned)(lch * 16));
                ldm4(ahi[mi], Ah + off);
                ldm4(alo[mi], Al + off);
                ldm4(bhi[mi], Bh + off);
                ldm4(blo[mi], Bl + off);
            }
#pragma unroll
            for (int mi = 0; mi < 2; mi++)
#pragma unroll
                for (int bi = 0; bi < 2; bi++) {
                    mma_bf16(acc[mi][bi * 2 + 0], ahi[mi], bhi[bi][0], bhi[bi][2]);
                    mma_bf16(acc[mi][bi * 2 + 1], ahi[mi], bhi[bi][1], bhi[bi][3]);
                    mma_bf16(acc[mi][bi * 2 + 0], ahi[mi], blo[bi][0], blo[bi][2]);
                    mma_bf16(acc[mi][bi * 2 + 1], ahi[mi], blo[bi][1], blo[bi][3]);
                    mma_bf16(acc[mi][bi * 2 + 0], alo[mi], bhi[bi][0], bhi[bi][2]);
                    mma_bf16(acc[mi][bi * 2 + 1], alo[mi], bhi[bi][1], bhi[bi][3]);
                }
        }
        __syncthreads();
    }

    // split-K partials: red[w][m][n]
    int gid = lane >> 2, tig = lane & 3;
#pragma unroll
    for (int mi = 0; mi < 2; mi++)
#pragma unroll
        for (int nj = 0; nj < 4; nj++) {
            int m = mi * 16 + gid, n = nj * 8 + tig * 2;
            *(float2*)&red[wid * 1024 + m * 32 + n] =
                make_float2(acc[mi][nj][0], acc[mi][nj][1]);
            *(float2*)&red[wid * 1024 + (m + 8) * 32 + n] =
                make_float2(acc[mi][nj][2], acc[mi][nj][3]);
        }
    __syncthreads();

    // fused cell update: thread -> (batch b, hidden jj)
    {
        int b = tid >> 3, jj = tid & 7;
        float gate[4] = {0.f, 0.f, 0.f, 0.f};
#pragma unroll
        for (int w = 0; w < 8; w++)
#pragma unroll
            for (int g = 0; g < 4; g++)
                gate[g] += red[w * 1024 + b * 32 + g * 8 + jj];
        int jg = j0 + jj;
        float vi = gate[0] + gxs[b * 32 + 0 + jj];
        float vj = gate[1] + gxs[b * 32 + 8 + jj];
        float vf = gate[2] + gxs[b * 32 + 16 + jj];
        float vo = gate[3] + gxs[b * 32 + 24 + jj];
        float cold = cs[b * 8 + jj];
        float si = 1.f / (1.f + expf(-vi));
        float sf = 1.f / (1.f + expf(-(vf + 1.f)));
        float so = 1.f / (1.f + expf(-vo));
        float cnew = sf * cold + si * tanhf(vj);
        float hnew = so * tanhf(cnew);
        c_st[b * H + jg] = cnew;
        __nv_bfloat16 hi = __float2bfloat16(hnew);
        __nv_bfloat16 lo = __float2bfloat16(hnew - __bfloat162float(hi));
        hout_hi[b * H + jg] = hi;
        hout_lo[b * H + jg] = lo;
    }
}

// ---------------- launcher ----------------
extern "C" void kernel_launch(void* const* d_in, const int* in_sizes, int n_in,
                              void* d_out, int out_size)
{
    const int*   input_seq = (const int*)d_in[0];
    const float* emb = (const float*)d_in[1];
    const float* W0  = (const float*)d_in[2];
    const float* b0  = (const float*)d_in[3];
    const float* W1  = (const float*)d_in[4];
    const float* b1  = (const float*)d_in[5];
    const float* Wd  = (const float*)d_in[6];
    const float* bd  = (const float*)d_in[7];
    float* out = (float*)d_out;
    (void)in_sizes; (void)n_in; (void)out_size;

    float *gxA, *gxB, *cbuf;
    __nv_bfloat16 *xahi, *xalo, *s0hi, *s0lo, *s1hi, *s1lo, *hzh, *hzl;
    __nv_bfloat16 *bhi, *blo, *w0xhi, *w0xlo, *w1xhi, *w1xlo;
    __nv_bfloat16 *wh0hi, *wh0lo, *wh1hi, *wh1lo;
    cudaGetSymbolAddress((void**)&gxA,  g_gxA);
    cudaGetSymbolAddress((void**)&gxB,  g_gxB);
    cudaGetSymbolAddress((void**)&cbuf, g_c);
    cudaGetSymbolAddress((void**)&xahi, g_xahi);
    cudaGetSymbolAddress((void**)&xalo, g_xalo);
    cudaGetSymbolAddress((void**)&s0hi, g_s0hi);
    cudaGetSymbolAddress((void**)&s0lo, g_s0lo);
    cudaGetSymbolAddress((void**)&s1hi, g_s1hi);
    cudaGetSymbolAddress((void**)&s1lo, g_s1lo);
    cudaGetSymbolAddress((void**)&hzh,  g_hzh);
    cudaGetSymbolAddress((void**)&hzl,  g_hzl);
    cudaGetSymbolAddress((void**)&bhi,  g_bhi);
    cudaGetSymbolAddress((void**)&blo,  g_blo);
    cudaGetSymbolAddress((void**)&w0xhi, g_w0xhi);
    cudaGetSymbolAddress((void**)&w0xlo, g_w0xlo);
    cudaGetSymbolAddress((void**)&w1xhi, g_w1xhi);
    cudaGetSymbolAddress((void**)&w1xlo, g_w1xlo);
    cudaGetSymbolAddress((void**)&wh0hi, g_wh0hi);
    cudaGetSymbolAddress((void**)&wh0lo, g_wh0lo);
    cudaGetSymbolAddress((void**)&wh1hi, g_wh1hi);
    cudaGetSymbolAddress((void**)&wh1lo, g_wh1lo);

    cudaFuncSetAttribute(hmma_gemm, cudaFuncAttributeMaxDynamicSharedMemorySize, DENSE_SMEM);
    cudaFuncSetAttribute(lstm_hmma, cudaFuncAttributeMaxDynamicSharedMemorySize, R_SMEM);

    // ---- one-time side stream + events (low priority so lstm steps schedule first) ----
    static cudaStream_t s2 = 0;
    static cudaEvent_t evFork, evG[32], evL1[32], evGx1Done, evDenseDone;
    if (!s2) {
        int lo_p, hi_p;
        cudaDeviceGetStreamPriorityRange(&lo_p, &hi_p);
        cudaStreamCreateWithPriority(&s2, cudaStreamNonBlocking, lo_p);
        cudaEventCreateWithFlags(&evFork, cudaEventDisableTiming);
        cudaEventCreateWithFlags(&evGx1Done, cudaEventDisableTiming);
        cudaEventCreateWithFlags(&evDenseDone, cudaEventDisableTiming);
        for (int i = 0; i < 32; i++) {
            cudaEventCreateWithFlags(&evG[i], cudaEventDisableTiming);
            cudaEventCreateWithFlags(&evL1[i], cudaEventDisableTiming);
        }
    }

    // ---- main-stream prologue ----
    zero_state_kernel<<<(B * H + 255) / 256, 256>>>();
    convert_wt<<<dim3(G / 32, H / 32), 256>>>(W0, w0xhi, w0xlo, G);
    convert_wt_perm<<<dim3(G / 32, H / 32), 256>>>(W0 + (size_t)E * G, wh0hi, wh0lo);
    convert_wt<<<dim3(G / 32, H / 32), 256>>>(W1, w1xhi, w1xlo, G);
    convert_wt_perm<<<dim3(G / 32, H / 32), 256>>>(W1 + (size_t)H * G, wh1hi, wh1lo);

    // fork side stream; Wd convert runs there (off critical path)
    cudaEventRecord(evFork, 0);
    cudaStreamWaitEvent(s2, evFork, 0);
    convert_wt<<<dim3(V / 32, H / 32), 256, 0, s2>>>(Wd, bhi, blo, V);

    // embedding (t-major, fused hi/lo split) + layer-0 input gates
    embed_split_kernel<<<BT, 256>>>(input_seq, emb);
    hmma_gemm<<<dim3(32, G / 128), 256, DENSE_SMEM>>>(
        xahi, xalo, w0xhi, w0xlo, b0, gxA, G, 0, 0);

    // ---- layer-0 recurrence; layer-1 gx GEMM overlapped in 4-step groups ----
    for (int grp = 0; grp < 32; grp++) {
        for (int k = 0; k < 4; k++) {
            int t = grp * 4 + k;
            const __nv_bfloat16* ihi = (t == 0) ? hzh : s0hi + (size_t)(t - 1) * B * H;
            const __nv_bfloat16* ilo = (t == 0) ? hzl : s0lo + (size_t)(t - 1) * B * H;
            lstm_hmma<<<128, 256, R_SMEM>>>(
                gxA, wh0hi, wh0lo, ihi, ilo,
                s0hi + (size_t)t * B * H, s0lo + (size_t)t * B * H, cbuf, t);
        }
        cudaEventRecord(evG[grp], 0);
        cudaStreamWaitEvent(s2, evG[grp], 0);
        hmma_gemm<<<dim3(1, G / 128), 256, DENSE_SMEM, s2>>>(
            s0hi, s0lo, w1xhi, w1xlo, b1, gxB, G, grp, 0);
    }
    cudaEventRecord(evGx1Done, s2);
    cudaStreamWaitEvent(0, evGx1Done, 0);

    // re-zero c for layer 1 (hz untouched by recurrence, stays zero)
    zero_state_kernel<<<(B * H + 255) / 256, 256>>>();

    // ---- layer-1 recurrence; dense projection overlapped in 4-step groups ----
    for (int grp = 0; grp < 32; grp++) {
        for (int k = 0; k < 4; k++) {
            int t = grp * 4 + k;
            const __nv_bfloat16* ihi = (t == 0) ? hzh : s1hi + (size_t)(t - 1) * B * H;
            const __nv_bfloat16* ilo = (t == 0) ? hzl : s1lo + (size_t)(t - 1) * B * H;
            lstm_hmma<<<128, 256, R_SMEM>>>(
                gxB, wh1hi, wh1lo, ihi, ilo,
                s1hi + (size_t)t * B * H, s1lo + (size_t)t * B * H, cbuf, t);
        }
        cudaEventRecord(evL1[grp], 0);
        cudaStreamWaitEvent(s2, evL1[grp], 0);
        hmma_gemm<<<dim3(1, V / 128), 256, DENSE_SMEM, s2>>>(
            s1hi, s1lo, bhi, blo, bd, out, V, grp, 1);
    }
    cudaEventRecord(evDenseDone, s2);
    cudaStreamWaitEvent(0, evDenseDone, 0);
}

// round 12
// speedup vs baseline: 1.0964x; 1.0964x over previous
#include <cuda_runtime.h>
#include <cuda_bf16.h>
#include <math.h>

#define B 32
#define T 128
#define BT 4096
#define E 1024
#define H 1024
#define G 4096
#define V 32000

typedef unsigned long long ull;

// ---------------- cp.async helpers ----------------
__device__ __forceinline__ void cp_async16_s(unsigned dst, const void* gptr) {
    asm volatile("cp.async.cg.shared.global [%0], [%1], 16;\n" :: "r"(dst), "l"(gptr));
}
__device__ __forceinline__ void cp_async_commit() {
    asm volatile("cp.async.commit_group;\n");
}
__device__ __forceinline__ void cp_async_wait_all() {
    asm volatile("cp.async.wait_group 0;\n" ::: "memory");
}
__device__ __forceinline__ void cp_async_wait_one() {
    asm volatile("cp.async.wait_group 1;\n" ::: "memory");
}

// ---------------- mma.sync / ldmatrix helpers ----------------
__device__ __forceinline__ void ldm4(unsigned* r, unsigned addr) {
    asm volatile("ldmatrix.sync.aligned.m8n8.x4.shared.b16 {%0,%1,%2,%3}, [%4];"
                 : "=r"(r[0]), "=r"(r[1]), "=r"(r[2]), "=r"(r[3]) : "r"(addr));
}
__device__ __forceinline__ void mma_bf16(float* c, const unsigned* a, unsigned b0, unsigned b1) {
    asm volatile(
        "mma.sync.aligned.m16n8k16.row.col.f32.bf16.bf16.f32 "
        "{%0,%1,%2,%3}, {%4,%5,%6,%7}, {%8,%9}, {%0,%1,%2,%3};"
        : "+f"(c[0]), "+f"(c[1]), "+f"(c[2]), "+f"(c[3])
        : "r"(a[0]), "r"(a[1]), "r"(a[2]), "r"(a[3]), "r"(b0), "r"(b1));
}
__device__ __forceinline__ unsigned swz(unsigned off) {
    return off ^ ((off >> 3) & 0x70);
}

// ---------------- device scratch ----------------
__device__ __align__(16) float g_gxA[BT * G];          // layer-0 input gates (t-major rows)
__device__ __align__(16) float g_gxB[BT * G];          // layer-1 input gates (t-major rows)
__device__ __align__(16) float g_c[B * H];
// t-major bf16 hi/lo activations
__device__ __align__(16) __nv_bfloat16 g_xahi[BT * H];
__device__ __align__(16) __nv_bfloat16 g_xalo[BT * H];
__device__ __align__(16) __nv_bfloat16 g_s0hi[BT * H];
__device__ __align__(16) __nv_bfloat16 g_s0lo[BT * H];
__device__ __align__(16) __nv_bfloat16 g_s1hi[BT * H];
__device__ __align__(16) __nv_bfloat16 g_s1lo[BT * H];
// zero h for t=0
__device__ __align__(16) __nv_bfloat16 g_hzh[B * H];
__device__ __align__(16) __nv_bfloat16 g_hzl[B * H];
// dense weights (transposed [n][k], hi/lo)
__device__ __align__(16) __nv_bfloat16 g_bhi[(size_t)V * H];
__device__ __align__(16) __nv_bfloat16 g_blo[(size_t)V * H];
// x-path weights, transposed [n][k]
__device__ __align__(16) __nv_bfloat16 g_w0xhi[G * H];
__device__ __align__(16) __nv_bfloat16 g_w0xlo[G * H];
__device__ __align__(16) __nv_bfloat16 g_w1xhi[G * H];
__device__ __align__(16) __nv_bfloat16 g_w1xlo[G * H];
// recurrent weights, transposed + gate-block permuted [prow][k]
__device__ __align__(16) __nv_bfloat16 g_wh0hi[G * H];
__device__ __align__(16) __nv_bfloat16 g_wh0lo[G * H];
__device__ __align__(16) __nv_bfloat16 g_wh1hi[G * H];
__device__ __align__(16) __nv_bfloat16 g_wh1lo[G * H];

// ---------------- embedding gather + bf16 hi/lo split (t-major) ----------------
__global__ void embed_split_kernel(const int* __restrict__ idx, const float* __restrict__ emb) {
    int r = blockIdx.x;                 // r = b*T + t
    int b = r >> 7, t = r & 127;
    int drow = t * B + b;
    int tok = idx[r];
    float4 v = ((const float4*)(emb + (size_t)tok * E))[threadIdx.x];
    int o = drow * H + threadIdx.x * 4;
    float f[4] = {v.x, v.y, v.z, v.w};
#pragma unroll
    for (int i = 0; i < 4; i++) {
        __nv_bfloat16 hi = __float2bfloat16(f[i]);
        __nv_bfloat16 lo = __float2bfloat16(f[i] - __bfloat162float(hi));
        g_xahi[o + i] = hi;
        g_xalo[o + i] = lo;
    }
}

// zero c and the t=0 h buffers
__global__ void zero_state_kernel() {
    int i = blockIdx.x * blockDim.x + threadIdx.x;
    if (i < B * H) {
        g_c[i] = 0.f;
        g_hzh[i] = __float2bfloat16(0.f);
        g_hzl[i] = __float2bfloat16(0.f);
    }
}

// ---------------- weight converts ----------------
// transpose-convert src[k][N] fp32 -> dhi/dlo[n][1024] bf16 (K = 1024)
__global__ __launch_bounds__(256) void convert_wt(
    const float* __restrict__ src, __nv_bfloat16* __restrict__ dhi,
    __nv_bfloat16* __restrict__ dlo, int N)
{
    __shared__ float tile[32][33];
    int tx = threadIdx.x & 31, ty = threadIdx.x >> 5;
    int n0 = blockIdx.x * 32, k0 = blockIdx.y * 32;
#pragma unroll
    for (int i = 0; i < 4; i++)
        tile[ty + 8 * i][tx] = src[(size_t)(k0 + ty + 8 * i) * N + n0 + tx];
    __syncthreads();
#pragma unroll
    for (int i = 0; i < 4; i++) {
        float v = tile[tx][ty + 8 * i];
        __nv_bfloat16 hi = __float2bfloat16(v);
        __nv_bfloat16 lo = __float2bfloat16(v - __bfloat162float(hi));
        size_t o = (size_t)(n0 + ty + 8 * i) * H + k0 + tx;
        dhi[o] = hi;
        dlo[o] = lo;
    }
}

// gate-block permuted: n = g*1024 + j -> prow = (j/8)*32 + g*8 + (j%8)
__global__ __launch_bounds__(256) void convert_wt_perm(
    const float* __restrict__ src, __nv_bfloat16* __restrict__ dhi,
    __nv_bfloat16* __restrict__ dlo)
{
    __shared__ float tile[32][33];
    int tx = threadIdx.x & 31, ty = threadIdx.x >> 5;
    int n0 = blockIdx.x * 32, k0 = blockIdx.y * 32;
#pragma unroll
    for (int i = 0; i < 4; i++)
        tile[ty + 8 * i][tx] = src[(size_t)(k0 + ty + 8 * i) * G + n0 + tx];
    __syncthreads();
#pragma unroll
    for (int i = 0; i < 4; i++) {
        float v = tile[tx][ty + 8 * i];
        __nv_bfloat16 hi = __float2bfloat16(v);
        __nv_bfloat16 lo = __float2bfloat16(v - __bfloat162float(hi));
        int n = n0 + ty + 8 * i;
        int g = n >> 10, j = n & 1023;
        int prow = (j >> 3) * 32 + g * 8 + (j & 7);
        size_t o = (size_t)prow * H + k0 + tx;
        dhi[o] = hi;
        dlo[o] = lo;
    }
}

// ---------------- generic HMMA GEMM: C = A @ B^T + bias (3-pass hi/lo) ----------------
// Block tile 128x128, 8 warps (2m x 4n), K chunks of 64, 3-stage cp.async pipeline.
// remap=1: A rows are t-major (row = t*32+b), C rows are b*T+t (dense out).
#define DTILE 16384
#define DSTAGE (4 * DTILE)
#define DENSE_SMEM (3 * DSTAGE)

__device__ __forceinline__ void hmma_load(
    unsigned sbase, int m0, int n0, int kc,
    const __nv_bfloat16* Ahi, const __nv_bfloat16* Alo,
    const __nv_bfloat16* Bhi, const __nv_bfloat16* Blo)
{
    int tid = threadIdx.x;
#pragma unroll
    for (int i = 0; i < 16; i++) {
        int idx = tid + i * 256;
        int tl = idx >> 10;           // 0=Ahi 1=Alo 2=Bhi 3=Blo
        int j = idx & 1023;
        int r = j >> 3, c = j & 7;
        const __nv_bfloat16* gb = (tl == 0) ? Ahi : (tl == 1) ? Alo
                                 : (tl == 2) ? Bhi : Blo;
        int grow = ((tl < 2) ? m0 : n0) + r;
        const __nv_bfloat16* src = gb + (size_t)grow * H + kc * 64 + c * 8;
        unsigned dst = sbase + tl * DTILE + swz((unsigned)(r * 128 + c * 16));
        cp_async16_s(dst, src);
    }
}

__global__ __launch_bounds__(256, 1) void hmma_gemm(
    const __nv_bfloat16* __restrict__ Ahi, const __nv_bfloat16* __restrict__ Alo,
    const __nv_bfloat16* __restrict__ Bhi, const __nv_bfloat16* __restrict__ Blo,
    const float* __restrict__ bias, float* __restrict__ C, int N, int remap)
{
    extern __shared__ __align__(128) char dsm[];
    unsigned sb = (unsigned)__cvta_generic_to_shared(dsm);
    int tid = threadIdx.x;
    int wid = tid >> 5, lane = tid & 31;
    int m0 = blockIdx.x * 128, n0 = blockIdx.y * 128;
    int wm = (wid & 1) * 64;
    int wn = (wid >> 1) * 32;
    int lrow = lane & 15, lch = lane >> 4;

    float acc[4][4][4];
#pragma unroll
    for (int mi = 0; mi < 4; mi++)
#pragma unroll
        for (int nj = 0; nj < 4; nj++)
#pragma unroll
            for (int q = 0; q < 4; q++) acc[mi][nj][q] = 0.f;

    hmma_load(sb + 0 * DSTAGE, m0, n0, 0, Ahi, Alo, Bhi, Blo);
    cp_async_commit();
    hmma_load(sb + 1 * DSTAGE, m0, n0, 1, Ahi, Alo, Bhi, Blo);
    cp_async_commit();

    int sidx = 0;   // stage of chunk kc
    for (int kc = 0; kc < 16; kc++) {
        if (kc < 15) cp_async_wait_one(); else cp_async_wait_all();
        __syncthreads();
        if (kc + 2 < 16) {
            int ls = sidx + 2; if (ls >= 3) ls -= 3;
            hmma_load(sb + ls * DSTAGE, m0, n0, kc + 2, Ahi, Alo, Bhi, Blo);
            cp_async_commit();
        }
        unsigned stage = sb + sidx * DSTAGE;

#pragma unroll
        for (int p = 0; p < 3; p++) {
            unsigned Ab = stage + ((p == 2) ? DTILE : 0);
            unsigned Bb = stage + 2 * DTILE + ((p == 1) ? DTILE : 0);
#pragma unroll
            for (int ks = 0; ks < 4; ks++) {
                unsigned a[4][4];
#pragma unroll
                for (int mi = 0; mi < 4; mi++) {
                    unsigned addr = Ab + swz((unsigned)((wm + mi * 16 + lrow) * 128
                                                        + ks * 32 + lch * 16));
                    ldm4(a[mi], addr);
                }
                unsigned bq[2][4];
#pragma unroll
                for (int bi = 0; bi < 2; bi++) {
                    unsigned addr = Bb + swz((unsigned)((wn + bi * 16 + lrow) * 128
                                                        + ks * 32 + lch * 16));
                    ldm4(bq[bi], addr);
                }
#pragma unroll
                for (int mi = 0; mi < 4; mi++)
#pragma unroll
                    for (int bi = 0; bi < 2; bi++) {
                        mma_bf16(acc[mi][bi * 2 + 0], a[mi], bq[bi][0], bq[bi][2]);
                        mma_bf16(acc[mi][bi * 2 + 1], a[mi], bq[bi][1], bq[bi][3]);
                    }
            }
        }
        if (++sidx >= 3) sidx = 0;
    }

    int gid = lane >> 2, tig = lane & 3;
#pragma unroll
    for (int mi = 0; mi < 4; mi++) {
#pragma unroll
        for (int nj = 0; nj < 4; nj++) {
            int gr0 = m0 + wm + mi * 16 + gid;
            int gr1 = gr0 + 8;
            int or0 = remap ? ((gr0 & 31) * T + (gr0 >> 5)) : gr0;
            int or1 = remap ? ((gr1 & 31) * T + (gr1 >> 5)) : gr1;
            int col = n0 + wn + nj * 8 + tig * 2;
            float b0 = bias[col], b1 = bias[col + 1];
            float2 o0, o1;
            o0.x = acc[mi][nj][0] + b0; o0.y = acc[mi][nj][1] + b1;
            o1.x = acc[mi][nj][2] + b0; o1.y = acc[mi][nj][3] + b1;
            *(float2*)(C + (size_t)or0 * N + col) = o0;
            *(float2*)(C + (size_t)or1 * N + col) = o1;
        }
    }
}

// ---------------- HMMA LSTM timestep v2 (validated in R11) ----------------
// 128 blocks; block bx owns hidden units j0 = bx*8..+7 (32 permuted weight rows).
// K = 1024 in 4 chunks of 256, double-buffered. gx slice + c prefetched to smem.
#define RSTG 65536
#define R_RED (2 * RSTG)
#define R_GX (R_RED + 32768)
#define R_CS (R_GX + 4096)
#define R_SMEM (R_CS + 1024)

__device__ __forceinline__ void lstm_stage_load(
    unsigned base, int kc,
    const __nv_bfloat16* hin_hi, const __nv_bfloat16* hin_lo,
    const __nv_bfloat16* whhi, const __nv_bfloat16* whlo, int n0)
{
    int tid = threadIdx.x;
#pragma unroll
    for (int i = 0; i < 16; i++) {
        int idx = tid + i * 256;
        int part = idx >> 10;         // 0=Ahi 1=Alo 2=Bhi 3=Blo
        int j = idx & 1023;
        int sub = j >> 8, jj = j & 255;
        int r = jj >> 3, c8 = jj & 7;
        int koff = kc * 256 + sub * 64 + c8 * 8;
        const __nv_bfloat16* src;
        if (part == 0)      src = hin_hi + r * H + koff;
        else if (part == 1) src = hin_lo + r * H + koff;
        else if (part == 2) src = whhi + (size_t)(n0 + r) * H + koff;
        else                src = whlo + (size_t)(n0 + r) * H + koff;
        unsigned dst = base + part * 16384 + sub * 4096 + swz((unsigned)(r * 128 + c8 * 16));
        cp_async16_s(dst, src);
    }
}

__global__ __launch_bounds__(256, 1) void lstm_hmma(
    const float* __restrict__ gx,
    const __nv_bfloat16* __restrict__ whhi, const __nv_bfloat16* __restrict__ whlo,
    const __nv_bfloat16* __restrict__ hin_hi, const __nv_bfloat16* __restrict__ hin_lo,
    __nv_bfloat16* __restrict__ hout_hi, __nv_bfloat16* __restrict__ hout_lo,
    float* __restrict__ c_st, int t)
{
    extern __shared__ __align__(128) char rsm[];
    unsigned sb = (unsigned)__cvta_generic_to_shared(rsm);
    float* red = (float*)(rsm + R_RED);
    float* gxs = (float*)(rsm + R_GX);
    float* cs  = (float*)(rsm + R_CS);
    int tid = threadIdx.x, wid = tid >> 5, lane = tid & 31;
    int n0 = blockIdx.x * 32;
    int j0 = blockIdx.x * 8;

    lstm_stage_load(sb, 0, hin_hi, hin_lo, whhi, whlo, n0);
    // prefetch gx slice and c state into smem
    {
        int b = tid >> 3, g = (tid >> 1) & 3, hf = tid & 1;
        cp_async16_s(sb + R_GX + (unsigned)(b * 32 + g * 8 + hf * 4) * 4,
                     gx + (size_t)(t * B + b) * G + g * H + j0 + hf * 4);
        if (tid < 64) {
            int b2 = tid >> 1, hf2 = tid & 1;
            cp_async16_s(sb + R_CS + (unsigned)(b2 * 8 + hf2 * 4) * 4,
                         c_st + b2 * H + j0 + hf2 * 4);
        }
    }
    cp_async_commit();

    float acc[2][4][4];
#pragma unroll
    for (int mi = 0; mi < 2; mi++)
#pragma unroll
        for (int nj = 0; nj < 4; nj++)
#pragma unroll
            for (int q = 0; q < 4; q++) acc[mi][nj][q] = 0.f;

    int sub = wid >> 1, half = wid & 1;
    int lrow = lane & 15, lch = lane >> 4;

    for (int c = 0; c < 4; c++) {
        int d = c & 1;
        unsigned stage = sb + d * RSTG;
        cp_async_wait_all();
        __syncthreads();
        if (c + 1 < 4) {
            lstm_stage_load(sb + (d ^ 1) * RSTG, c + 1, hin_hi, hin_lo, whhi, whlo, n0);
            cp_async_commit();
        }

        unsigned Ah = stage + sub * 4096;
        unsigned Al = stage + 16384 + sub * 4096;
        unsigned Bh = stage + 32768 + sub * 4096;
        unsigned Bl = stage + 49152 + sub * 4096;

#pragma unroll
        for (int ki = 0; ki < 2; ki++) {
            unsigned kb = (unsigned)((half * 2 + ki) * 32);
            unsigned ahi[2][4], alo[2][4], bhi[2][4], blo[2][4];
#pragma unroll
            for (int mi = 0; mi < 2; mi++) {
                unsigned off = swz((unsigned)((mi * 16 + lrow) * 128) + kb + (unsigned)(lch * 16));
                ldm4(ahi[mi], Ah + off);
                ldm4(alo[mi], Al + off);
                ldm4(bhi[mi], Bh + off);
                ldm4(blo[mi], Bl + off);
            }
#pragma unroll
            for (int mi = 0; mi < 2; mi++)
#pragma unroll
                for (int bi = 0; bi < 2; bi++) {
                    mma_bf16(acc[mi][bi * 2 + 0], ahi[mi], bhi[bi][0], bhi[bi][2]);
                    mma_bf16(acc[mi][bi * 2 + 1], ahi[mi], bhi[bi][1], bhi[bi][3]);
                    mma_bf16(acc[mi][bi * 2 + 0], ahi[mi], blo[bi][0], blo[bi][2]);
                    mma_bf16(acc[mi][bi * 2 + 1], ahi[mi], blo[bi][1], blo[bi][3]);
                    mma_bf16(acc[mi][bi * 2 + 0], alo[mi], bhi[bi][0], bhi[bi][2]);
                    mma_bf16(acc[mi][bi * 2 + 1], alo[mi], bhi[bi][1], bhi[bi][3]);
                }
        }
        __syncthreads();
    }

    // split-K partials: red[w][m][n]
    int gid = lane >> 2, tig = lane & 3;
#pragma unroll
    for (int mi = 0; mi < 2; mi++)
#pragma unroll
        for (int nj = 0; nj < 4; nj++) {
            int m = mi * 16 + gid, n = nj * 8 + tig * 2;
            *(float2*)&red[wid * 1024 + m * 32 + n] =
                make_float2(acc[mi][nj][0], acc[mi][nj][1]);
            *(float2*)&red[wid * 1024 + (m + 8) * 32 + n] =
                make_float2(acc[mi][nj][2], acc[mi][nj][3]);
        }
    __syncthreads();

    // fused cell update: thread -> (batch b, hidden jj)
    {
        int b = tid >> 3, jj = tid & 7;
        float gate[4] = {0.f, 0.f, 0.f, 0.f};
#pragma unroll
        for (int w = 0; w < 8; w++)
#pragma unroll
            for (int g = 0; g < 4; g++)
                gate[g] += red[w * 1024 + b * 32 + g * 8 + jj];
        int jg = j0 + jj;
        float vi = gate[0] + gxs[b * 32 + 0 + jj];
        float vj = gate[1] + gxs[b * 32 + 8 + jj];
        float vf = gate[2] + gxs[b * 32 + 16 + jj];
        float vo = gate[3] + gxs[b * 32 + 24 + jj];
        float cold = cs[b * 8 + jj];
        float si = 1.f / (1.f + expf(-vi));
        float sf = 1.f / (1.f + expf(-(vf + 1.f)));
        float so = 1.f / (1.f + expf(-vo));
        float cnew = sf * cold + si * tanhf(vj);
        float hnew = so * tanhf(cnew);
        c_st[b * H + jg] = cnew;
        __nv_bfloat16 hi = __float2bfloat16(hnew);
        __nv_bfloat16 lo = __float2bfloat16(hnew - __bfloat162float(hi));
        hout_hi[b * H + jg] = hi;
        hout_lo[b * H + jg] = lo;
    }
}

// ---------------- launcher (single stream, sequential) ----------------
extern "C" void kernel_launch(void* const* d_in, const int* in_sizes, int n_in,
                              void* d_out, int out_size)
{
    const int*   input_seq = (const int*)d_in[0];
    const float* emb = (const float*)d_in[1];
    const float* W0  = (const float*)d_in[2];
    const float* b0  = (const float*)d_in[3];
    const float* W1  = (const float*)d_in[4];
    const float* b1  = (const float*)d_in[5];
    const float* Wd  = (const float*)d_in[6];
    const float* bd  = (const float*)d_in[7];
    float* out = (float*)d_out;
    (void)in_sizes; (void)n_in; (void)out_size;

    float *gxA, *gxB, *cbuf;
    __nv_bfloat16 *xahi, *xalo, *s0hi, *s0lo, *s1hi, *s1lo, *hzh, *hzl;
    __nv_bfloat16 *bhi, *blo, *w0xhi, *w0xlo, *w1xhi, *w1xlo;
    __nv_bfloat16 *wh0hi, *wh0lo, *wh1hi, *wh1lo;
    cudaGetSymbolAddress((void**)&gxA,  g_gxA);
    cudaGetSymbolAddress((void**)&gxB,  g_gxB);
    cudaGetSymbolAddress((void**)&cbuf, g_c);
    cudaGetSymbolAddress((void**)&xahi, g_xahi);
    cudaGetSymbolAddress((void**)&xalo, g_xalo);
    cudaGetSymbolAddress((void**)&s0hi, g_s0hi);
    cudaGetSymbolAddress((void**)&s0lo, g_s0lo);
    cudaGetSymbolAddress((void**)&s1hi, g_s1hi);
    cudaGetSymbolAddress((void**)&s1lo, g_s1lo);
    cudaGetSymbolAddress((void**)&hzh,  g_hzh);
    cudaGetSymbolAddress((void**)&hzl,  g_hzl);
    cudaGetSymbolAddress((void**)&bhi,  g_bhi);
    cudaGetSymbolAddress((void**)&blo,  g_blo);
    cudaGetSymbolAddress((void**)&w0xhi, g_w0xhi);
    cudaGetSymbolAddress((void**)&w0xlo, g_w0xlo);
    cudaGetSymbolAddress((void**)&w1xhi, g_w1xhi);
    cudaGetSymbolAddress((void**)&w1xlo, g_w1xlo);
    cudaGetSymbolAddress((void**)&wh0hi, g_wh0hi);
    cudaGetSymbolAddress((void**)&wh0lo, g_wh0lo);
    cudaGetSymbolAddress((void**)&wh1hi, g_wh1hi);
    cudaGetSymbolAddress((void**)&wh1lo, g_wh1lo);

    cudaFuncSetAttribute(hmma_gemm, cudaFuncAttributeMaxDynamicSharedMemorySize, DENSE_SMEM);
    cudaFuncSetAttribute(lstm_hmma, cudaFuncAttributeMaxDynamicSharedMemorySize, R_SMEM);

    // ---- prologue: state + weight converts ----
    zero_state_kernel<<<(B * H + 255) / 256, 256>>>();
    convert_wt<<<dim3(G / 32, H / 32), 256>>>(W0, w0xhi, w0xlo, G);
    convert_wt_perm<<<dim3(G / 32, H / 32), 256>>>(W0 + (size_t)E * G, wh0hi, wh0lo);
    convert_wt<<<dim3(G / 32, H / 32), 256>>>(W1, w1xhi, w1xlo, G);
    convert_wt_perm<<<dim3(G / 32, H / 32), 256>>>(W1 + (size_t)H * G, wh1hi, wh1lo);
    convert_wt<<<dim3(V / 32, H / 32), 256>>>(Wd, bhi, blo, V);

    // ---- embedding (t-major, fused hi/lo split) + layer-0 input gates ----
    embed_split_kernel<<<BT, 256>>>(input_seq, emb);
    hmma_gemm<<<dim3(BT / 128, G / 128), 256, DENSE_SMEM>>>(
        xahi, xalo, w0xhi, w0xlo, b0, gxA, G, 0);

    // ---- layer-0 recurrence ----
    for (int t = 0; t < T; t++) {
        const __nv_bfloat16* ihi = (t == 0) ? hzh : s0hi + (size_t)(t - 1) * B * H;
        const __nv_bfloat16* ilo = (t == 0) ? hzl : s0lo + (size_t)(t - 1) * B * H;
        lstm_hmma<<<128, 256, R_SMEM>>>(
            gxA, wh0hi, wh0lo, ihi, ilo,
            s0hi + (size_t)t * B * H, s0lo + (size_t)t * B * H, cbuf, t);
    }

    // ---- layer-1 input gates ----
    hmma_gemm<<<dim3(BT / 128, G / 128), 256, DENSE_SMEM>>>(
        s0hi, s0lo, w1xhi, w1xlo, b1, gxB, G, 0);

    // re-zero c for layer 1 (hz stays zero)
    zero_state_kernel<<<(B * H + 255) / 256, 256>>>();

    // ---- layer-1 recurrence ----
    for (int t = 0; t < T; t++) {
        const __nv_bfloat16* ihi = (t == 0) ? hzh : s1hi + (size_t)(t - 1) * B * H;
        const __nv_bfloat16* ilo = (t == 0) ? hzl : s1lo + (size_t)(t - 1) * B * H;
        lstm_hmma<<<128, 256, R_SMEM>>>(
            gxB, wh1hi, wh1lo, ihi, ilo,
            s1hi + (size_t)t * B * H, s1lo + (size_t)t * B * H, cbuf, t);
    }

    // ---- dense projection (t-major A, remapped output rows) ----
    hmma_gemm<<<dim3(BT / 128, V / 128), 256, DENSE_SMEM>>>(
        s1hi, s1lo, bhi, blo, bd, out, V, 1);
}